// round 11
// baseline (speedup 1.0000x reference)
#include <cuda_runtime.h>

typedef unsigned long long u64;

#define HALF     512
#define BATCH    8192
#define DEPTH    20
#define TB       16          // batch columns per block (4 bq threads x 4 cols)
#define NTHREADS 128         // 32 row-threads x 4 batch-quad threads
#define NBLOCKS  (BATCH / TB)

// Pre-packed coefficients: {(c,c),(s,s)} as 2x f32x2 in one 16B entry.
// P1-type layers (l%10 < 5) stored PERMUTED: natural pair p -> slot
// (p&15)*32 + (p>>4), so BOTH pass types address coefs as m*32 + rt; a warp's
// 8 consecutive rt values read 128 consecutive bytes (1 wavefront), broadcast
// across the 4 bq lanes.
__device__ ulonglong2 g_pk[DEPTH * HALF];

__global__ void prep_kernel(const float* __restrict__ ang) {
    int i = blockIdx.x * blockDim.x + threadIdx.x;
    if (i < DEPTH * HALF) {
        const int l = i / HALF;
        const int p = i % HALF;
        float s, c;
        sincosf(ang[i], &s, &c);
        u64 cc, ss;
        asm("mov.b64 %0, {%1, %1};" : "=l"(cc) : "f"(c));
        asm("mov.b64 %0, {%1, %1};" : "=l"(ss) : "f"(s));
        const int slot = ((l % 10) < 5) ? ((p & 15) * 32 + (p >> 4)) : p;
        g_pk[l * HALF + slot] = make_ulonglong2(cc, ss);
    }
}

// ---- packed f32x2 helpers (sm_100) ----
__device__ __forceinline__ u64 mul2(u64 a, u64 b) {
    u64 d; asm("mul.rn.f32x2 %0, %1, %2;" : "=l"(d) : "l"(a), "l"(b)); return d;
}
__device__ __forceinline__ u64 fma2(u64 a, u64 b, u64 c) {
    u64 d; asm("fma.rn.f32x2 %0, %1, %2, %3;" : "=l"(d) : "l"(a), "l"(b), "l"(c)); return d;
}

// Givens rotation on one packed pair: y0 = c*x0 + s*x1 ; y1 = -s*x0 + c*x1
__device__ __forceinline__ void rot(u64& x0, u64& x1, u64 cc, u64 ss, u64 ns) {
    const u64 y0 = fma2(cc, x0, mul2(ss, x1));
    const u64 y1 = fma2(ns, x0, mul2(cc, x1));
    x0 = y0; x1 = y1;
}

// Five butterfly levels fully in registers on 4 batch columns (Xa, Xb -> 4
// independent FMA chains per rotation). Flattened into 40 half-steps of 2
// coefs each, with a dist-1 pipelined packed-coefficient stream (16 buffer
// regs -- same pressure as R10, keeps total under the 255 cap).
// Coef slot = m*32 + rt; pairs (j, j+2^l), j = ((m>>l)<<(l+1)) | (m & (2^l-1)).
__device__ __forceinline__ void pass5(u64* Xa, u64* Xb, const ulonglong2* __restrict__ lt) {
    ulonglong2 cf[2];
    cf[0] = __ldg(lt + 0);
    cf[1] = __ldg(lt + 32);

#pragma unroll
    for (int v = 0; v < 40; ++v) {
        const int l = v >> 3;
        ulonglong2 nf[2];
        if (v < 39) {
            const int l2 = (v + 1) >> 3;
            const int mb = ((v + 1) & 7) * 2;
            nf[0] = __ldg(lt + l2 * HALF + (mb + 0) * 32);
            nf[1] = __ldg(lt + l2 * HALF + (mb + 1) * 32);
        }
#pragma unroll
        for (int t = 0; t < 2; ++t) {
            const int m  = (v & 7) * 2 + t;
            const int sg = 1 << l;
            const int j  = ((m >> l) << (l + 1)) | (m & (sg - 1));
            const u64 ns = cf[t].y ^ 0x8000000080000000ULL;
            rot(Xa[j], Xa[j + sg], cf[t].x, cf[t].y, ns);
            rot(Xb[j], Xb[j + sg], cf[t].x, cf[t].y, ns);
        }
        cf[0] = nf[0]; cf[1] = nf[1];
    }
}

// Smem swizzle in 16B units (hardware-verified in R5/R10):
// addr(row,bq) = ((row ^ ((row>>5)&1)) << 2) | bq. For warp = 8 rt x 4 bq,
// both exchange groupings hit each 128B bank-group with exactly 4 lanes ->
// 512B warp accesses at the 4-phase minimum. Bijective.
#define ADRA(j) (baseA + (((j) ^ eA) << 2))                 // row = rt*32+j
#define ADRB(j) ((j) * 128 + (((j) & 1) ? baseB1 : baseB0)) // row = rt+32j

extern "C" __global__ void __launch_bounds__(NTHREADS, 2)
butterfly_kernel(const float* __restrict__ X, float* __restrict__ Y)
{
    extern __shared__ ulonglong2 tile[];   // 1024 rows x 4 bq x 16B = 64 KB

    const int bq = threadIdx.x & 3;        // batch-quad (4 cols) 0..3
    const int rt = threadIdx.x >> 2;       // row-thread 0..31
    const long long bb = (long long)blockIdx.x * TB + bq * 4;

    const int eA     = rt & 1;
    const int baseA  = rt * 128 + bq;
    const int baseB0 = (rt << 2) + bq;
    const int baseB1 = ((rt ^ 1) << 2) + bq;

    u64 Xa[32], Xb[32];                    // 32 rows x 4 batch columns

    // Load, layout A (reg j = row rt*32+j); .cg keeps L1 for the coef table.
#pragma unroll
    for (int j = 0; j < 32; ++j) {
        const float4 v = __ldcg(
            reinterpret_cast<const float4*>(X + (long long)(rt * 32 + j) * BATCH + bb));
        asm("mov.b64 %0, {%2, %3}; mov.b64 %1, {%4, %5};"
            : "=l"(Xa[j]), "=l"(Xb[j]) : "f"(v.x), "f"(v.y), "f"(v.z), "f"(v.w));
    }

    const ulonglong2* lt = g_pk + rt;

#pragma unroll 1
    for (int sp = 0; sp < 2; ++sp) {
        // layers sp*10 .. sp*10+4 (register strides 1..16 in layout A)
        pass5(Xa, Xb, lt + (sp * 10) * HALF);

        // exchange A -> B
        __syncthreads();
#pragma unroll
        for (int j = 0; j < 32; ++j) tile[ADRA(j)] = make_ulonglong2(Xa[j], Xb[j]);
        __syncthreads();
#pragma unroll
        for (int j = 0; j < 32; ++j) {
            const ulonglong2 v = tile[ADRB(j)];
            Xa[j] = v.x; Xb[j] = v.y;
        }

        // layers sp*10+5 .. sp*10+9 (strides 32..512 in layout B)
        pass5(Xa, Xb, lt + (sp * 10 + 5) * HALF);

        if (sp == 0) {
            // exchange B -> A
            __syncthreads();
#pragma unroll
            for (int j = 0; j < 32; ++j) tile[ADRB(j)] = make_ulonglong2(Xa[j], Xb[j]);
            __syncthreads();
#pragma unroll
            for (int j = 0; j < 32; ++j) {
                const ulonglong2 v = tile[ADRA(j)];
                Xa[j] = v.x; Xb[j] = v.y;
            }
        }
    }

    // Store, layout B (reg j = row rt+32j), .cg to bypass L1.
#pragma unroll
    for (int j = 0; j < 32; ++j) {
        float x, y, z, w;
        asm("mov.b64 {%0, %1}, %4; mov.b64 {%2, %3}, %5;"
            : "=f"(x), "=f"(y), "=f"(z), "=f"(w) : "l"(Xa[j]), "l"(Xb[j]));
        __stcg(reinterpret_cast<float4*>(Y + (long long)(rt + 32 * j) * BATCH + bb),
               make_float4(x, y, z, w));
    }
}

extern "C" void kernel_launch(void* const* d_in, const int* in_sizes, int n_in,
                              void* d_out, int out_size)
{
    const float* X = (const float*)d_in[0];
    const float* A = (const float*)d_in[1];
    if (n_in >= 2 && in_sizes[0] < in_sizes[1]) {   // defensive: X is the big one
        const float* t = X; X = A; A = t;
    }
    float* Y = (float*)d_out;

    cudaFuncSetAttribute(butterfly_kernel,
                         cudaFuncAttributeMaxDynamicSharedMemorySize, 65536);

    prep_kernel<<<(DEPTH * HALF + 255) / 256, 256>>>(A);
    butterfly_kernel<<<NBLOCKS, NTHREADS, 65536>>>(X, Y);
}

// round 12
// speedup vs baseline: 1.0009x; 1.0009x over previous
#include <cuda_runtime.h>

typedef unsigned long long u64;

#define HALF     512
#define BATCH    8192
#define DEPTH    20
#define TB       16          // 16 batch columns per block: 4 warps x 4 cols
#define NTHREADS 128
#define NBLOCKS  (BATCH / TB)

// Scalar (c, s) coefficients, 8B each. P1-type layers (l%10 < 5) stored
// PERMUTED: natural pair p -> slot (p&15)*32 + (p>>4), so BOTH pass types
// address coefs as m*32 + rt (rt = lane).
__device__ float2 g_cs[DEPTH * HALF];

__global__ void sincos_kernel(const float* __restrict__ ang) {
    int i = blockIdx.x * blockDim.x + threadIdx.x;
    if (i < DEPTH * HALF) {
        const int l = i / HALF;
        const int p = i % HALF;
        float s, c;
        sincosf(ang[i], &s, &c);
        const int slot = ((l % 10) < 5) ? ((p & 15) * 32 + (p >> 4)) : p;
        g_cs[l * HALF + slot] = make_float2(c, s);
    }
}

// ---- packed f32x2 helpers (sm_100) ----
__device__ __forceinline__ u64 pk2(float v) {
    u64 r; asm("mov.b64 %0, {%1, %1};" : "=l"(r) : "f"(v)); return r;
}
__device__ __forceinline__ u64 mul2(u64 a, u64 b) {
    u64 d; asm("mul.rn.f32x2 %0, %1, %2;" : "=l"(d) : "l"(a), "l"(b)); return d;
}
__device__ __forceinline__ u64 fma2(u64 a, u64 b, u64 c) {
    u64 d; asm("fma.rn.f32x2 %0, %1, %2, %3;" : "=l"(d) : "l"(a), "l"(b), "l"(c)); return d;
}

// Givens rotation on one packed pair: y0 = c*x0 + s*x1 ; y1 = -s*x0 + c*x1
__device__ __forceinline__ void rot(u64& x0, u64& x1, u64 cc, u64 ss, u64 ns) {
    const u64 y0 = fma2(cc, x0, mul2(ss, x1));
    const u64 y1 = fma2(ns, x0, mul2(cc, x1));
    x0 = y0; x1 = y1;
}

// Five butterfly levels in registers on 4 batch columns (4 independent FMA
// chains per rotation), flattened into 20 q-steps with dist-1 coef prefetch.
// Coef slot = m*32 + rt; pairs (j, j+2^l), j = ((m>>l)<<(l+1)) | (m & (2^l-1)).
__device__ __forceinline__ void pass5(u64* Xa, u64* Xb, const float2* __restrict__ lt) {
    float2 cf[4];
#pragma unroll
    for (int t = 0; t < 4; ++t) cf[t] = __ldg(lt + t * 32);

#pragma unroll
    for (int u = 0; u < 20; ++u) {
        const int l = u >> 2;
        const int q = u & 3;
        float2 nf[4];
        if (u < 19) {
            const int l2 = (u + 1) >> 2;
            const int q2 = (u + 1) & 3;
#pragma unroll
            for (int t = 0; t < 4; ++t)
                nf[t] = __ldg(lt + l2 * HALF + (q2 * 4 + t) * 32);
        }
#pragma unroll
        for (int t = 0; t < 4; ++t) {
            const int m  = q * 4 + t;
            const int sg = 1 << l;
            const int j  = ((m >> l) << (l + 1)) | (m & (sg - 1));
            const u64 cc = pk2(cf[t].x);
            const u64 ss = pk2(cf[t].y);
            const u64 ns = ss ^ 0x8000000080000000ULL;
            rot(Xa[j], Xa[j + sg], cc, ss, ns);
            rot(Xb[j], Xb[j + sg], cc, ss, ns);
        }
#pragma unroll
        for (int t = 0; t < 4; ++t) cf[t] = nf[t];
    }
}

// Tile address in 16B units, 1024 rows x 4 col-groups:
//   addr16(row,cg) = (row>>1)*8 + ((((row&1)<<2)|cg) ^ ((row>>1)^(row>>5))&7)
// Enumerated: 4 lanes per 128B bank-group (optimal 4-phase for 512B warp
// accesses) in all four patterns used below; bijective per cg.
//   pattern A (row=rt*32+j): rt*128 + (j>>1)*8 + (KA(j) ^ ewr)
//   pattern B (row=rt+32i):  (rt>>1)*8 + i*128 + ((i&7) ^ ezb)
//   pattern L (row=i*32+lr): (lr>>1)*8 + i*128 + ((i&7) ^ ezl)
#define KA(j)   ((((j) & 1) << 2) ^ (((j) >> 1) & 7))
#define ADRA(j) (rt * 128 + (((j) >> 1) << 3) + (KA(j) ^ ewr))
#define ADRB(i) (baseB + (i) * 128 + (((i) & 7) ^ ezb))
#define ADRL(i) (baseL + (i) * 128 + (((i) & 7) ^ ezl))

extern "C" __global__ void __launch_bounds__(NTHREADS, 2)
butterfly_kernel(const float* __restrict__ X, float* __restrict__ Y)
{
    extern __shared__ ulonglong2 tile[];   // 1024 x 4 x 16B = 64 KB

    const int tid = threadIdx.x;
    const int rt  = tid & 31;              // lane = row-thread
    const int w   = tid >> 5;              // warp = column-group (4 cols)
    const int lr  = tid >> 2;              // staging row-lane 0..31
    const int cg  = tid & 3;               // staging col-group

    const int ewr  = w ^ (rt & 7);
    const int baseB = (rt >> 1) << 3;
    const int ezb  = ((rt & 1) << 2) ^ w ^ ((rt >> 1) & 7);
    const int baseL = (lr >> 1) << 3;
    const int ezl  = ((lr & 1) << 2) ^ cg ^ ((lr >> 1) & 7);

    const long long colW = (long long)blockIdx.x * TB + w * 4;   // compute cols
    const long long colL = (long long)blockIdx.x * TB + cg * 4;  // staging cols

    u64 Xa[32], Xb[32];                    // 32 rows x 4 batch columns

    // ---- stage in: gmem (coalesced 8 rows x 64B per warp) -> tile ----
#pragma unroll
    for (int i = 0; i < 32; ++i) {
        const float4 v = __ldcg(
            reinterpret_cast<const float4*>(X + (long long)(i * 32 + lr) * BATCH + colL));
        ulonglong2 e;
        asm("mov.b64 %0, {%2, %3}; mov.b64 %1, {%4, %5};"
            : "=l"(e.x), "=l"(e.y) : "f"(v.x), "f"(v.y), "f"(v.z), "f"(v.w));
        tile[ADRL(i)] = e;
    }
    __syncthreads();

    // read layout A (reg j = row rt*32+j) from this warp's strip
#pragma unroll
    for (int j = 0; j < 32; ++j) {
        const ulonglong2 v = tile[ADRA(j)];
        Xa[j] = v.x; Xb[j] = v.y;
    }

    const float2* lt = g_cs + rt;

#pragma unroll 1
    for (int sp = 0; sp < 2; ++sp) {
        // layers sp*10 .. sp*10+4 (register strides 1..16, layout A)
        pass5(Xa, Xb, lt + (sp * 10) * HALF);

        // warp-local exchange A -> B
        __syncwarp();
#pragma unroll
        for (int j = 0; j < 32; ++j) tile[ADRA(j)] = make_ulonglong2(Xa[j], Xb[j]);
        __syncwarp();
#pragma unroll
        for (int j = 0; j < 32; ++j) {
            const ulonglong2 v = tile[ADRB(j)];
            Xa[j] = v.x; Xb[j] = v.y;
        }

        // layers sp*10+5 .. sp*10+9 (strides 32..512, layout B)
        pass5(Xa, Xb, lt + (sp * 10 + 5) * HALF);

        if (sp == 0) {
            // warp-local exchange B -> A
            __syncwarp();
#pragma unroll
            for (int j = 0; j < 32; ++j) tile[ADRB(j)] = make_ulonglong2(Xa[j], Xb[j]);
            __syncwarp();
#pragma unroll
            for (int j = 0; j < 32; ++j) {
                const ulonglong2 v = tile[ADRA(j)];
                Xa[j] = v.x; Xb[j] = v.y;
            }
        }
    }

    // ---- stage out: layout B -> tile -> gmem (coalesced) ----
    __syncwarp();
#pragma unroll
    for (int j = 0; j < 32; ++j) tile[ADRB(j)] = make_ulonglong2(Xa[j], Xb[j]);
    __syncthreads();
#pragma unroll
    for (int i = 0; i < 32; ++i) {
        const ulonglong2 e = tile[ADRL(i)];
        float x, y, z, wv;
        asm("mov.b64 {%0, %1}, %4; mov.b64 {%2, %3}, %5;"
            : "=f"(x), "=f"(y), "=f"(z), "=f"(wv) : "l"(e.x), "l"(e.y));
        __stcg(reinterpret_cast<float4*>(Y + (long long)(i * 32 + lr) * BATCH + colL),
               make_float4(x, y, z, wv));
    }
}

extern "C" void kernel_launch(void* const* d_in, const int* in_sizes, int n_in,
                              void* d_out, int out_size)
{
    const float* X = (const float*)d_in[0];
    const float* A = (const float*)d_in[1];
    if (n_in >= 2 && in_sizes[0] < in_sizes[1]) {   // defensive: X is the big one
        const float* t = X; X = A; A = t;
    }
    float* Y = (float*)d_out;

    cudaFuncSetAttribute(butterfly_kernel,
                         cudaFuncAttributeMaxDynamicSharedMemorySize, 65536);

    sincos_kernel<<<(DEPTH * HALF + 255) / 256, 256>>>(A);
    butterfly_kernel<<<NBLOCKS, NTHREADS, 65536>>>(X, Y);
}